// round 2
// baseline (speedup 1.0000x reference)
#include <cuda_runtime.h>
#include <cstddef>

#define N_EMBD 1024
#define T_SEQ  2048
#define BATCH  2
#define NROWS  (BATCH * T_SEQ)      // 4096
#define NHEAD  16
#define HDIM   64
#define EPS_LN 1e-5f

// ---------------- scratch (device globals; no allocations allowed) -------------
__device__ float g_xn1[(size_t)NROWS * N_EMBD];       // 16 MB
__device__ float g_qkv[(size_t)NROWS * 3 * N_EMBD];   // 48 MB
__device__ float g_y  [(size_t)NROWS * N_EMBD];       // 16 MB
__device__ float g_x1 [(size_t)NROWS * N_EMBD];       // 16 MB
__device__ float g_xn2[(size_t)NROWS * N_EMBD];       // 16 MB
__device__ float g_h  [(size_t)NROWS * 4 * N_EMBD];   // 64 MB

// ---------------- LayerNorm: one block per row of 1024 ------------------------
__global__ void layernorm_kernel(const float* __restrict__ x,
                                 const float* __restrict__ g,
                                 const float* __restrict__ b,
                                 float* __restrict__ out) {
    __shared__ float sh[8];
    __shared__ float stats[2];
    int row = blockIdx.x;
    int tid = threadIdx.x;                // 256 threads, 4 floats each
    const float4* xr = (const float4*)(x + (size_t)row * N_EMBD);
    float4 v = xr[tid];
    float s = v.x + v.y + v.z + v.w;
    #pragma unroll
    for (int o = 16; o > 0; o >>= 1) s += __shfl_xor_sync(0xffffffffu, s, o);
    if ((tid & 31) == 0) sh[tid >> 5] = s;
    __syncthreads();
    if (tid == 0) {
        float t = 0.f;
        #pragma unroll
        for (int i = 0; i < 8; i++) t += sh[i];
        stats[0] = t * (1.0f / N_EMBD);
    }
    __syncthreads();
    float mu = stats[0];
    float dx = v.x - mu, dy = v.y - mu, dz = v.z - mu, dw = v.w - mu;
    float ss = dx * dx + dy * dy + dz * dz + dw * dw;
    #pragma unroll
    for (int o = 16; o > 0; o >>= 1) ss += __shfl_xor_sync(0xffffffffu, ss, o);
    if ((tid & 31) == 0) sh[tid >> 5] = ss;
    __syncthreads();
    if (tid == 0) {
        float t = 0.f;
        #pragma unroll
        for (int i = 0; i < 8; i++) t += sh[i];
        stats[1] = rsqrtf(t * (1.0f / N_EMBD) + EPS_LN);
    }
    __syncthreads();
    float rstd = stats[1];
    int c = tid * 4;
    float4 gv = *(const float4*)(g + c);
    float4 bv = *(const float4*)(b + c);
    float4 o4;
    o4.x = dx * rstd * gv.x + bv.x;
    o4.y = dy * rstd * gv.y + bv.y;
    o4.z = dz * rstd * gv.z + bv.z;
    o4.w = dw * rstd * gv.w + bv.w;
    ((float4*)(out + (size_t)row * N_EMBD))[tid] = o4;
}

// ---------------- SGEMM 128x128x8, 256 threads, 8x8/thread --------------------
// C[M,N] = A[M,K] @ B[K,N] + bias ; EPI: 0 = bias, 1 = bias+GELU, 2 = bias+residual
template <int EPI>
__global__ __launch_bounds__(256) void gemm_kernel(
    const float* __restrict__ A, const float* __restrict__ B,
    const float* __restrict__ bias, const float* __restrict__ res,
    float* __restrict__ C, int M, int N, int K) {
    constexpr int BM = 128, BN = 128, BK = 8;
    __shared__ float As[BK][BM];
    __shared__ float Bs[BK][BN];

    int tid = threadIdx.x;
    int tx = tid & 15, ty = tid >> 4;
    int row0 = ty * 8, col0 = tx * 8;
    int bx = blockIdx.x, by = blockIdx.y;

    int arow = tid >> 1;          // 0..127
    int acol = (tid & 1) * 4;     // 0 or 4
    int brow = tid >> 5;          // 0..7
    int bcol = (tid & 31) * 4;    // 0..124

    const float* Aptr = A + (size_t)(by * BM + arow) * K + acol;
    const float* Bptr = B + (size_t)brow * N + bx * BN + bcol;

    float acc[8][8];
    #pragma unroll
    for (int i = 0; i < 8; i++)
        #pragma unroll
        for (int j = 0; j < 8; j++) acc[i][j] = 0.f;

    for (int k0 = 0; k0 < K; k0 += BK) {
        float4 av = *(const float4*)Aptr;
        float4 bv = *(const float4*)Bptr;
        As[acol + 0][arow] = av.x;
        As[acol + 1][arow] = av.y;
        As[acol + 2][arow] = av.z;
        As[acol + 3][arow] = av.w;
        *(float4*)&Bs[brow][bcol] = bv;
        __syncthreads();
        #pragma unroll
        for (int k = 0; k < BK; k++) {
            float4 a0 = *(const float4*)&As[k][row0];
            float4 a1 = *(const float4*)&As[k][row0 + 4];
            float4 b0 = *(const float4*)&Bs[k][col0];
            float4 b1 = *(const float4*)&Bs[k][col0 + 4];
            float a[8] = {a0.x, a0.y, a0.z, a0.w, a1.x, a1.y, a1.z, a1.w};
            float bb[8] = {b0.x, b0.y, b0.z, b0.w, b1.x, b1.y, b1.z, b1.w};
            #pragma unroll
            for (int i = 0; i < 8; i++)
                #pragma unroll
                for (int j = 0; j < 8; j++) acc[i][j] += a[i] * bb[j];
        }
        __syncthreads();
        Aptr += BK;
        Bptr += (size_t)BK * N;
    }

    int cbase = bx * BN + col0;
    float bi[8];
    #pragma unroll
    for (int j = 0; j < 8; j++) bi[j] = bias[cbase + j];

    #pragma unroll
    for (int i = 0; i < 8; i++) {
        int r = by * BM + row0 + i;
        float* Crow = C + (size_t)r * N + cbase;
        const float* Rrow = (EPI == 2) ? (res + (size_t)r * N + cbase) : nullptr;
        float v[8];
        #pragma unroll
        for (int j = 0; j < 8; j++) {
            float t = acc[i][j] + bi[j];
            if (EPI == 1) t = t * 0.5f * (1.0f + erff(t * 0.70710678118654752f));
            if (EPI == 2) t += Rrow[j];
            v[j] = t;
        }
        *(float4*)(Crow)     = make_float4(v[0], v[1], v[2], v[3]);
        *(float4*)(Crow + 4) = make_float4(v[4], v[5], v[6], v[7]);
    }
}

// ---------------- Flash attention: 64-q-row tiles, online softmax --------------
// grid: (T/64 q-tiles, B*H), block: 256 threads. qkv rows: [q(1024) k(1024) v(1024)]
#define ATT_SMEM_FLOATS (4 * 64 * 65)
__global__ __launch_bounds__(256) void attn_kernel(const float* __restrict__ qkv,
                                                   float* __restrict__ y) {
    extern __shared__ float smem[];
    float* Qs = smem;               // [64][65]
    float* Ks = Qs + 64 * 65;
    float* Vs = Ks + 64 * 65;
    float* Ps = Vs + 64 * 65;

    int qt = blockIdx.x;            // 0..31
    int bh = blockIdx.y;            // 0..31
    int b  = bh >> 4;
    int h  = bh & 15;
    int tid = threadIdx.x;
    int tx = tid & 15, ty = tid >> 4;
    int r0 = ty * 4, c0 = tx * 4;   // 4x4 tile per thread
    const int C3 = 3 * N_EMBD;

    // load Q tile (64 x 64)
    {
        const float* qp = qkv + (size_t)(b * T_SEQ + qt * 64) * C3 + h * HDIM;
        #pragma unroll
        for (int i = 0; i < 4; i++) {
            int fi = tid + i * 256;          // float4 index 0..1023
            int row = fi >> 4, c4 = (fi & 15) * 4;
            float4 v = *(const float4*)(qp + (size_t)row * C3 + c4);
            Qs[row * 65 + c4 + 0] = v.x;
            Qs[row * 65 + c4 + 1] = v.y;
            Qs[row * 65 + c4 + 2] = v.z;
            Qs[row * 65 + c4 + 3] = v.w;
        }
    }

    float acc[4][4];
    float m[4], l[4];
    #pragma unroll
    for (int i = 0; i < 4; i++) {
        m[i] = -1e30f; l[i] = 0.f;
        #pragma unroll
        for (int j = 0; j < 4; j++) acc[i][j] = 0.f;
    }

    for (int kt = 0; kt <= qt; kt++) {
        __syncthreads();  // previous tile's reads of Ks/Vs/Ps complete
        // load K, V tiles (64 x 64 each)
        const float* kp = qkv + (size_t)(b * T_SEQ + kt * 64) * C3 + N_EMBD + h * HDIM;
        const float* vp = kp + N_EMBD;
        #pragma unroll
        for (int i = 0; i < 4; i++) {
            int fi = tid + i * 256;
            int row = fi >> 4, c4 = (fi & 15) * 4;
            float4 kv = *(const float4*)(kp + (size_t)row * C3 + c4);
            float4 vv = *(const float4*)(vp + (size_t)row * C3 + c4);
            Ks[row * 65 + c4 + 0] = kv.x;
            Ks[row * 65 + c4 + 1] = kv.y;
            Ks[row * 65 + c4 + 2] = kv.z;
            Ks[row * 65 + c4 + 3] = kv.w;
            Vs[row * 65 + c4 + 0] = vv.x;
            Vs[row * 65 + c4 + 1] = vv.y;
            Vs[row * 65 + c4 + 2] = vv.z;
            Vs[row * 65 + c4 + 3] = vv.w;
        }
        __syncthreads();

        // S = Q K^T (4x4 per thread)
        float s[4][4];
        #pragma unroll
        for (int i = 0; i < 4; i++)
            #pragma unroll
            for (int j = 0; j < 4; j++) s[i][j] = 0.f;
        #pragma unroll 8
        for (int k = 0; k < 64; k++) {
            float a[4], bb[4];
            #pragma unroll
            for (int i = 0; i < 4; i++) a[i] = Qs[(r0 + i) * 65 + k];
            #pragma unroll
            for (int j = 0; j < 4; j++) bb[j] = Ks[(c0 + j) * 65 + k];
            #pragma unroll
            for (int i = 0; i < 4; i++)
                #pragma unroll
                for (int j = 0; j < 4; j++) s[i][j] += a[i] * bb[j];
        }
        // scale + causal mask
        bool diag = (kt == qt);
        #pragma unroll
        for (int i = 0; i < 4; i++) {
            int qg = qt * 64 + r0 + i;
            #pragma unroll
            for (int j = 0; j < 4; j++) {
                int kg = kt * 64 + c0 + j;
                float sv = s[i][j] * 0.125f;   // 1/sqrt(64)
                s[i][j] = (diag && kg > qg) ? -1e30f : sv;
            }
        }
        // online softmax (row stats across 16 lanes sharing ty)
        #pragma unroll
        for (int i = 0; i < 4; i++) {
            float mloc = s[i][0];
            #pragma unroll
            for (int j = 1; j < 4; j++) mloc = fmaxf(mloc, s[i][j]);
            #pragma unroll
            for (int o = 1; o < 16; o <<= 1)
                mloc = fmaxf(mloc, __shfl_xor_sync(0xffffffffu, mloc, o));
            float mnew = fmaxf(m[i], mloc);
            float corr = expf(m[i] - mnew);
            float lsum = 0.f;
            #pragma unroll
            for (int j = 0; j < 4; j++) {
                float p = expf(s[i][j] - mnew);
                s[i][j] = p;
                lsum += p;
            }
            #pragma unroll
            for (int o = 1; o < 16; o <<= 1)
                lsum += __shfl_xor_sync(0xffffffffu, lsum, o);
            l[i] = l[i] * corr + lsum;
            m[i] = mnew;
            #pragma unroll
            for (int j = 0; j < 4; j++) acc[i][j] *= corr;
        }
        // publish P
        #pragma unroll
        for (int i = 0; i < 4; i++)
            #pragma unroll
            for (int j = 0; j < 4; j++) Ps[(r0 + i) * 65 + (c0 + j)] = s[i][j];
        __syncthreads();

        // acc += P @ V
        #pragma unroll 8
        for (int k = 0; k < 64; k++) {
            float a[4], bb[4];
            #pragma unroll
            for (int i = 0; i < 4; i++) a[i] = Ps[(r0 + i) * 65 + k];
            #pragma unroll
            for (int j = 0; j < 4; j++) bb[j] = Vs[k * 65 + (c0 + j)];
            #pragma unroll
            for (int i = 0; i < 4; i++)
                #pragma unroll
                for (int j = 0; j < 4; j++) acc[i][j] += a[i] * bb[j];
        }
    }

    // write output (divide by l)
    #pragma unroll
    for (int i = 0; i < 4; i++) {
        int qg = qt * 64 + r0 + i;
        float inv = 1.0f / l[i];
        float* yp = y + (size_t)(b * T_SEQ + qg) * N_EMBD + h * HDIM + c0;
        *(float4*)yp = make_float4(acc[i][0] * inv, acc[i][1] * inv,
                                   acc[i][2] * inv, acc[i][3] * inv);
    }
}

// ---------------------------------- launcher -----------------------------------
extern "C" void kernel_launch(void* const* d_in, const int* in_sizes, int n_in,
                              void* d_out, int out_size) {
    const float* x      = (const float*)d_in[0];
    const float* ln1_g  = (const float*)d_in[1];
    const float* ln1_b  = (const float*)d_in[2];
    const float* W_attn = (const float*)d_in[3];
    const float* b_attn = (const float*)d_in[4];
    const float* W_proj = (const float*)d_in[5];
    const float* b_proj = (const float*)d_in[6];
    const float* ln2_g  = (const float*)d_in[7];
    const float* ln2_b  = (const float*)d_in[8];
    const float* W_fc   = (const float*)d_in[9];
    const float* b_fc   = (const float*)d_in[10];
    const float* W_fc2  = (const float*)d_in[11];
    const float* b_fc2  = (const float*)d_in[12];
    float* out = (float*)d_out;

    float *xn1, *qkv, *y, *x1, *xn2, *hb;
    cudaGetSymbolAddress((void**)&xn1, g_xn1);
    cudaGetSymbolAddress((void**)&qkv, g_qkv);
    cudaGetSymbolAddress((void**)&y,   g_y);
    cudaGetSymbolAddress((void**)&x1,  g_x1);
    cudaGetSymbolAddress((void**)&xn2, g_xn2);
    cudaGetSymbolAddress((void**)&hb,  g_h);

    const int attn_smem = ATT_SMEM_FLOATS * (int)sizeof(float);  // 66560 B
    cudaFuncSetAttribute(attn_kernel, cudaFuncAttributeMaxDynamicSharedMemorySize,
                         attn_smem);

    // 1) ln1
    layernorm_kernel<<<NROWS, 256>>>(x, ln1_g, ln1_b, xn1);
    // 2) qkv = xn1 @ W_attn + b_attn     [4096,1024]x[1024,3072]
    gemm_kernel<0><<<dim3(3072 / 128, NROWS / 128), 256>>>(
        xn1, W_attn, b_attn, nullptr, qkv, NROWS, 3072, 1024);
    // 3) attention
    attn_kernel<<<dim3(T_SEQ / 64, BATCH * NHEAD), 256, attn_smem>>>(qkv, y);
    // 4) x1 = x + y @ W_proj + b_proj    [4096,1024]x[1024,1024]
    gemm_kernel<2><<<dim3(1024 / 128, NROWS / 128), 256>>>(
        y, W_proj, b_proj, x, x1, NROWS, 1024, 1024);
    // 5) ln2
    layernorm_kernel<<<NROWS, 256>>>(x1, ln2_g, ln2_b, xn2);
    // 6) h = gelu(xn2 @ W_fc + b_fc)     [4096,1024]x[1024,4096]
    gemm_kernel<1><<<dim3(4096 / 128, NROWS / 128), 256>>>(
        xn2, W_fc, b_fc, nullptr, hb, NROWS, 4096, 1024);
    // 7) out = x1 + h @ W_fc2 + b_fc2    [4096,4096]x[4096,1024]
    gemm_kernel<2><<<dim3(1024 / 128, NROWS / 128), 256>>>(
        hb, W_fc2, b_fc2, x1, out, NROWS, 1024, 4096);
}

// round 3
// speedup vs baseline: 2.2219x; 2.2219x over previous
#include <cuda_runtime.h>
#include <cstdint>
#include <cstddef>

#define N_EMBD 1024
#define T_SEQ  2048
#define BATCH  2
#define NROWS  (BATCH * T_SEQ)      // 4096
#define NHEAD  16
#define HDIM   64
#define EPS_LN 1e-5f

// ---------------- scratch (device globals; no allocations allowed) -------------
__device__ float g_xn1[(size_t)NROWS * N_EMBD];
__device__ float g_qkv[(size_t)NROWS * 3 * N_EMBD];
__device__ float g_y  [(size_t)NROWS * N_EMBD];
__device__ float g_x1 [(size_t)NROWS * N_EMBD];
__device__ float g_xn2[(size_t)NROWS * N_EMBD];
__device__ float g_h  [(size_t)NROWS * 4 * N_EMBD];

// ---------------- LayerNorm: one block per row of 1024 ------------------------
__global__ void layernorm_kernel(const float* __restrict__ x,
                                 const float* __restrict__ g,
                                 const float* __restrict__ b,
                                 float* __restrict__ out) {
    __shared__ float sh[8];
    __shared__ float stats[2];
    int row = blockIdx.x;
    int tid = threadIdx.x;                // 256 threads, 4 floats each
    const float4* xr = (const float4*)(x + (size_t)row * N_EMBD);
    float4 v = xr[tid];
    float s = v.x + v.y + v.z + v.w;
    #pragma unroll
    for (int o = 16; o > 0; o >>= 1) s += __shfl_xor_sync(0xffffffffu, s, o);
    if ((tid & 31) == 0) sh[tid >> 5] = s;
    __syncthreads();
    if (tid == 0) {
        float t = 0.f;
        #pragma unroll
        for (int i = 0; i < 8; i++) t += sh[i];
        stats[0] = t * (1.0f / N_EMBD);
    }
    __syncthreads();
    float mu = stats[0];
    float dx = v.x - mu, dy = v.y - mu, dz = v.z - mu, dw = v.w - mu;
    float ss = dx * dx + dy * dy + dz * dz + dw * dw;
    #pragma unroll
    for (int o = 16; o > 0; o >>= 1) ss += __shfl_xor_sync(0xffffffffu, ss, o);
    if ((tid & 31) == 0) sh[tid >> 5] = ss;
    __syncthreads();
    if (tid == 0) {
        float t = 0.f;
        #pragma unroll
        for (int i = 0; i < 8; i++) t += sh[i];
        stats[1] = rsqrtf(t * (1.0f / N_EMBD) + EPS_LN);
    }
    __syncthreads();
    float rstd = stats[1];
    int c = tid * 4;
    float4 gv = *(const float4*)(g + c);
    float4 bv = *(const float4*)(b + c);
    float4 o4;
    o4.x = dx * rstd * gv.x + bv.x;
    o4.y = dy * rstd * gv.y + bv.y;
    o4.z = dz * rstd * gv.z + bv.z;
    o4.w = dw * rstd * gv.w + bv.w;
    ((float4*)(out + (size_t)row * N_EMBD))[tid] = o4;
}

// ---------------- TF32 tensor-core GEMM --------------------------------------
// C[M,N] = A[M,K] @ B[K,N] + bias ; EPI: 0 = bias, 1 = bias+GELU, 2 = bias+residual
// BM=128, BN=128, BK=16; 8 warps (2Mx4N), warp tile 64x32; mma.m16n8k8 tf32.
__device__ __forceinline__ uint32_t f2tf32(float f) {
    uint32_t u;
    asm("cvt.rn.tf32.f32 %0, %1;" : "=r"(u) : "f"(f));
    return u;
}

#define AS_STRIDE 20    // padded words per A row  (conflict-free frag LDS, 16B-aligned)
#define BS_STRIDE 136   // padded words per B row  (conflict-free frag LDS, 16B-aligned)

template <int EPI>
__global__ __launch_bounds__(256, 2) void gemm_tf32_kernel(
    const float* __restrict__ A, const float* __restrict__ B,
    const float* __restrict__ bias, const float* __restrict__ res,
    float* __restrict__ C, int M, int N, int K) {
    __shared__ uint32_t As[2][128 * AS_STRIDE];  // [m][k] padded
    __shared__ uint32_t Bs[2][16 * BS_STRIDE];   // [k][n] padded

    const int tid = threadIdx.x;
    const int bx = blockIdx.x, by = blockIdx.y;
    const int warp = tid >> 5, lane = tid & 31;
    const int wm = warp >> 2, wn = warp & 3;          // 2 x 4 warp grid
    const int group = lane >> 2, tig = lane & 3;

    // global-load indexing (2 float4 each for A and B per thread)
    const int a_row0 = tid >> 2;                 // 0..63  (+64 for second)
    const int a_c    = (tid & 3) * 4;            // 0,4,8,12
    const int b_row0 = tid >> 5;                 // 0..7   (+8 for second)
    const int b_c    = (tid & 31) * 4;           // 0..124

    const float* Ap0 = A + (size_t)(by * 128 + a_row0) * K + a_c;
    const float* Ap1 = Ap0 + (size_t)64 * K;
    const float* Bp0 = B + (size_t)b_row0 * N + bx * 128 + b_c;
    const float* Bp1 = Bp0 + (size_t)8 * N;

    float acc[4][4][4];
    #pragma unroll
    for (int mi = 0; mi < 4; mi++)
        #pragma unroll
        for (int ni = 0; ni < 4; ni++)
            #pragma unroll
            for (int r = 0; r < 4; r++) acc[mi][ni][r] = 0.f;

    const int nk = K / 16;

    // prologue: tile 0 -> buf 0
    {
        float4 a0 = *(const float4*)Ap0;
        float4 a1 = *(const float4*)Ap1;
        float4 b0 = *(const float4*)Bp0;
        float4 b1 = *(const float4*)Bp1;
        uint32_t* as = &As[0][0];
        uint32_t* bs = &Bs[0][0];
        as[(a_row0)      * AS_STRIDE + a_c + 0] = f2tf32(a0.x);
        as[(a_row0)      * AS_STRIDE + a_c + 1] = f2tf32(a0.y);
        as[(a_row0)      * AS_STRIDE + a_c + 2] = f2tf32(a0.z);
        as[(a_row0)      * AS_STRIDE + a_c + 3] = f2tf32(a0.w);
        as[(a_row0 + 64) * AS_STRIDE + a_c + 0] = f2tf32(a1.x);
        as[(a_row0 + 64) * AS_STRIDE + a_c + 1] = f2tf32(a1.y);
        as[(a_row0 + 64) * AS_STRIDE + a_c + 2] = f2tf32(a1.z);
        as[(a_row0 + 64) * AS_STRIDE + a_c + 3] = f2tf32(a1.w);
        bs[(b_row0)     * BS_STRIDE + b_c + 0] = f2tf32(b0.x);
        bs[(b_row0)     * BS_STRIDE + b_c + 1] = f2tf32(b0.y);
        bs[(b_row0)     * BS_STRIDE + b_c + 2] = f2tf32(b0.z);
        bs[(b_row0)     * BS_STRIDE + b_c + 3] = f2tf32(b0.w);
        bs[(b_row0 + 8) * BS_STRIDE + b_c + 0] = f2tf32(b1.x);
        bs[(b_row0 + 8) * BS_STRIDE + b_c + 1] = f2tf32(b1.y);
        bs[(b_row0 + 8) * BS_STRIDE + b_c + 2] = f2tf32(b1.z);
        bs[(b_row0 + 8) * BS_STRIDE + b_c + 3] = f2tf32(b1.w);
    }
    __syncthreads();

    for (int it = 0; it < nk; it++) {
        // prefetch next tile into registers
        float4 pa0, pa1, pb0, pb1;
        const bool have_next = (it + 1 < nk);
        if (have_next) {
            const float* ap0 = Ap0 + (it + 1) * 16;
            const float* ap1 = Ap1 + (it + 1) * 16;
            const float* bp0 = Bp0 + (size_t)(it + 1) * 16 * N;
            const float* bp1 = Bp1 + (size_t)(it + 1) * 16 * N;
            pa0 = *(const float4*)ap0;
            pa1 = *(const float4*)ap1;
            pb0 = *(const float4*)bp0;
            pb1 = *(const float4*)bp1;
        }

        // compute from smem buf it&1
        const uint32_t* as = &As[it & 1][0];
        const uint32_t* bs = &Bs[it & 1][0];
        #pragma unroll
        for (int ks = 0; ks < 2; ks++) {
            const int kb = ks * 8;
            uint32_t afr[4][4];
            #pragma unroll
            for (int mi = 0; mi < 4; mi++) {
                int rb = wm * 64 + mi * 16;
                afr[mi][0] = as[(rb + group)     * AS_STRIDE + kb + tig];
                afr[mi][1] = as[(rb + group + 8) * AS_STRIDE + kb + tig];
                afr[mi][2] = as[(rb + group)     * AS_STRIDE + kb + tig + 4];
                afr[mi][3] = as[(rb + group + 8) * AS_STRIDE + kb + tig + 4];
            }
            uint32_t bfr[4][2];
            #pragma unroll
            for (int ni = 0; ni < 4; ni++) {
                int cb = wn * 32 + ni * 8;
                bfr[ni][0] = bs[(kb + tig)     * BS_STRIDE + cb + group];
                bfr[ni][1] = bs[(kb + tig + 4) * BS_STRIDE + cb + group];
            }
            #pragma unroll
            for (int mi = 0; mi < 4; mi++)
                #pragma unroll
                for (int ni = 0; ni < 4; ni++) {
                    asm volatile(
                        "mma.sync.aligned.m16n8k8.row.col.f32.tf32.tf32.f32 "
                        "{%0,%1,%2,%3}, {%4,%5,%6,%7}, {%8,%9}, {%0,%1,%2,%3};"
                        : "+f"(acc[mi][ni][0]), "+f"(acc[mi][ni][1]),
                          "+f"(acc[mi][ni][2]), "+f"(acc[mi][ni][3])
                        : "r"(afr[mi][0]), "r"(afr[mi][1]),
                          "r"(afr[mi][2]), "r"(afr[mi][3]),
                          "r"(bfr[ni][0]), "r"(bfr[ni][1]));
                }
        }

        // store prefetched tile to other buffer
        if (have_next) {
            uint32_t* asn = &As[(it + 1) & 1][0];
            uint32_t* bsn = &Bs[(it + 1) & 1][0];
            asn[(a_row0)      * AS_STRIDE + a_c + 0] = f2tf32(pa0.x);
            asn[(a_row0)      * AS_STRIDE + a_c + 1] = f2tf32(pa0.y);
            asn[(a_row0)      * AS_STRIDE + a_c + 2] = f2tf32(pa0.z);
            asn[(a_row0)      * AS_STRIDE + a_c + 3] = f2tf32(pa0.w);
            asn[(a_row0 + 64) * AS_STRIDE + a_c + 0] = f2tf32(pa1.x);
            asn[(a_row0 + 64) * AS_STRIDE + a_c + 1] = f2tf32(pa1.y);
            asn[(a_row0 + 64) * AS_STRIDE + a_c + 2] = f2tf32(pa1.z);
            asn[(a_row0 + 64) * AS_STRIDE + a_c + 3] = f2tf32(pa1.w);
            bsn[(b_row0)     * BS_STRIDE + b_c + 0] = f2tf32(pb0.x);
            bsn[(b_row0)     * BS_STRIDE + b_c + 1] = f2tf32(pb0.y);
            bsn[(b_row0)     * BS_STRIDE + b_c + 2] = f2tf32(pb0.z);
            bsn[(b_row0)     * BS_STRIDE + b_c + 3] = f2tf32(pb0.w);
            bsn[(b_row0 + 8) * BS_STRIDE + b_c + 0] = f2tf32(pb1.x);
            bsn[(b_row0 + 8) * BS_STRIDE + b_c + 1] = f2tf32(pb1.y);
            bsn[(b_row0 + 8) * BS_STRIDE + b_c + 2] = f2tf32(pb1.z);
            bsn[(b_row0 + 8) * BS_STRIDE + b_c + 3] = f2tf32(pb1.w);
        }
        __syncthreads();
    }

    // epilogue
    #pragma unroll
    for (int ni = 0; ni < 4; ni++) {
        int col = bx * 128 + wn * 32 + ni * 8 + 2 * tig;
        float bi0 = bias[col], bi1 = bias[col + 1];
        #pragma unroll
        for (int mi = 0; mi < 4; mi++) {
            int row = by * 128 + wm * 64 + mi * 16 + group;
            #pragma unroll
            for (int h = 0; h < 2; h++) {    // h=0: rows row, h=1: row+8
                int r = row + h * 8;
                float v0 = acc[mi][ni][2 * h + 0] + bi0;
                float v1 = acc[mi][ni][2 * h + 1] + bi1;
                if (EPI == 1) {
                    v0 = v0 * 0.5f * (1.0f + erff(v0 * 0.70710678118654752f));
                    v1 = v1 * 0.5f * (1.0f + erff(v1 * 0.70710678118654752f));
                }
                if (EPI == 2) {
                    const float* rr = res + (size_t)r * N + col;
                    v0 += rr[0];
                    v1 += rr[1];
                }
                float2* cp = (float2*)(C + (size_t)r * N + col);
                *cp = make_float2(v0, v1);
            }
        }
    }
}

// ---------------- Flash attention: 64-q-row tiles, online softmax --------------
#define ATT_SMEM_FLOATS (4 * 64 * 65)
__global__ __launch_bounds__(256) void attn_kernel(const float* __restrict__ qkv,
                                                   float* __restrict__ y) {
    extern __shared__ float smem[];
    float* Qs = smem;               // [64][65]
    float* Ks = Qs + 64 * 65;
    float* Vs = Ks + 64 * 65;
    float* Ps = Vs + 64 * 65;

    int qt = blockIdx.x;
    int bh = blockIdx.y;
    int b  = bh >> 4;
    int h  = bh & 15;
    int tid = threadIdx.x;
    int tx = tid & 15, ty = tid >> 4;
    int r0 = ty * 4, c0 = tx * 4;
    const int C3 = 3 * N_EMBD;

    {
        const float* qp = qkv + (size_t)(b * T_SEQ + qt * 64) * C3 + h * HDIM;
        #pragma unroll
        for (int i = 0; i < 4; i++) {
            int fi = tid + i * 256;
            int row = fi >> 4, c4 = (fi & 15) * 4;
            float4 v = *(const float4*)(qp + (size_t)row * C3 + c4);
            Qs[row * 65 + c4 + 0] = v.x;
            Qs[row * 65 + c4 + 1] = v.y;
            Qs[row * 65 + c4 + 2] = v.z;
            Qs[row * 65 + c4 + 3] = v.w;
        }
    }

    float acc[4][4];
    float m[4], l[4];
    #pragma unroll
    for (int i = 0; i < 4; i++) {
        m[i] = -1e30f; l[i] = 0.f;
        #pragma unroll
        for (int j = 0; j < 4; j++) acc[i][j] = 0.f;
    }

    for (int kt = 0; kt <= qt; kt++) {
        __syncthreads();
        const float* kp = qkv + (size_t)(b * T_SEQ + kt * 64) * C3 + N_EMBD + h * HDIM;
        const float* vp = kp + N_EMBD;
        #pragma unroll
        for (int i = 0; i < 4; i++) {
            int fi = tid + i * 256;
            int row = fi >> 4, c4 = (fi & 15) * 4;
            float4 kv = *(const float4*)(kp + (size_t)row * C3 + c4);
            float4 vv = *(const float4*)(vp + (size_t)row * C3 + c4);
            Ks[row * 65 + c4 + 0] = kv.x;
            Ks[row * 65 + c4 + 1] = kv.y;
            Ks[row * 65 + c4 + 2] = kv.z;
            Ks[row * 65 + c4 + 3] = kv.w;
            Vs[row * 65 + c4 + 0] = vv.x;
            Vs[row * 65 + c4 + 1] = vv.y;
            Vs[row * 65 + c4 + 2] = vv.z;
            Vs[row * 65 + c4 + 3] = vv.w;
        }
        __syncthreads();

        float s[4][4];
        #pragma unroll
        for (int i = 0; i < 4; i++)
            #pragma unroll
            for (int j = 0; j < 4; j++) s[i][j] = 0.f;
        #pragma unroll 8
        for (int k = 0; k < 64; k++) {
            float a[4], bb[4];
            #pragma unroll
            for (int i = 0; i < 4; i++) a[i] = Qs[(r0 + i) * 65 + k];
            #pragma unroll
            for (int j = 0; j < 4; j++) bb[j] = Ks[(c0 + j) * 65 + k];
            #pragma unroll
            for (int i = 0; i < 4; i++)
                #pragma unroll
                for (int j = 0; j < 4; j++) s[i][j] += a[i] * bb[j];
        }
        bool diag = (kt == qt);
        #pragma unroll
        for (int i = 0; i < 4; i++) {
            int qg = qt * 64 + r0 + i;
            #pragma unroll
            for (int j = 0; j < 4; j++) {
                int kg = kt * 64 + c0 + j;
                float sv = s[i][j] * 0.125f;
                s[i][j] = (diag && kg > qg) ? -1e30f : sv;
            }
        }
        #pragma unroll
        for (int i = 0; i < 4; i++) {
            float mloc = s[i][0];
            #pragma unroll
            for (int j = 1; j < 4; j++) mloc = fmaxf(mloc, s[i][j]);
            #pragma unroll
            for (int o = 1; o < 16; o <<= 1)
                mloc = fmaxf(mloc, __shfl_xor_sync(0xffffffffu, mloc, o));
            float mnew = fmaxf(m[i], mloc);
            float corr = expf(m[i] - mnew);
            float lsum = 0.f;
            #pragma unroll
            for (int j = 0; j < 4; j++) {
                float p = expf(s[i][j] - mnew);
                s[i][j] = p;
                lsum += p;
            }
            #pragma unroll
            for (int o = 1; o < 16; o <<= 1)
                lsum += __shfl_xor_sync(0xffffffffu, lsum, o);
            l[i] = l[i] * corr + lsum;
            m[i] = mnew;
            #pragma unroll
            for (int j = 0; j < 4; j++) acc[i][j] *= corr;
        }
        #pragma unroll
        for (int i = 0; i < 4; i++)
            #pragma unroll
            for (int j = 0; j < 4; j++) Ps[(r0 + i) * 65 + (c0 + j)] = s[i][j];
        __syncthreads();

        #pragma unroll 8
        for (int k = 0; k < 64; k++) {
            float a[4], bb[4];
            #pragma unroll
            for (int i = 0; i < 4; i++) a[i] = Ps[(r0 + i) * 65 + k];
            #pragma unroll
            for (int j = 0; j < 4; j++) bb[j] = Vs[k * 65 + (c0 + j)];
            #pragma unroll
            for (int i = 0; i < 4; i++)
                #pragma unroll
                for (int j = 0; j < 4; j++) acc[i][j] += a[i] * bb[j];
        }
    }

    #pragma unroll
    for (int i = 0; i < 4; i++) {
        int qg = qt * 64 + r0 + i;
        float inv = 1.0f / l[i];
        float* yp = y + (size_t)(b * T_SEQ + qg) * N_EMBD + h * HDIM + c0;
        *(float4*)yp = make_float4(acc[i][0] * inv, acc[i][1] * inv,
                                   acc[i][2] * inv, acc[i][3] * inv);
    }
}

// ---------------------------------- launcher -----------------------------------
extern "C" void kernel_launch(void* const* d_in, const int* in_sizes, int n_in,
                              void* d_out, int out_size) {
    const float* x      = (const float*)d_in[0];
    const float* ln1_g  = (const float*)d_in[1];
    const float* ln1_b  = (const float*)d_in[2];
    const float* W_attn = (const float*)d_in[3];
    const float* b_attn = (const float*)d_in[4];
    const float* W_proj = (const float*)d_in[5];
    const float* b_proj = (const float*)d_in[6];
    const float* ln2_g  = (const float*)d_in[7];
    const float* ln2_b  = (const float*)d_in[8];
    const float* W_fc   = (const float*)d_in[9];
    const float* b_fc   = (const float*)d_in[10];
    const float* W_fc2  = (const float*)d_in[11];
    const float* b_fc2  = (const float*)d_in[12];
    float* out = (float*)d_out;

    float *xn1, *qkv, *y, *x1, *xn2, *hb;
    cudaGetSymbolAddress((void**)&xn1, g_xn1);
    cudaGetSymbolAddress((void**)&qkv, g_qkv);
    cudaGetSymbolAddress((void**)&y,   g_y);
    cudaGetSymbolAddress((void**)&x1,  g_x1);
    cudaGetSymbolAddress((void**)&xn2, g_xn2);
    cudaGetSymbolAddress((void**)&hb,  g_h);

    const int attn_smem = ATT_SMEM_FLOATS * (int)sizeof(float);
    cudaFuncSetAttribute(attn_kernel, cudaFuncAttributeMaxDynamicSharedMemorySize,
                         attn_smem);

    // 1) ln1
    layernorm_kernel<<<NROWS, 256>>>(x, ln1_g, ln1_b, xn1);
    // 2) qkv = xn1 @ W_attn + b_attn     [4096,1024]x[1024,3072]
    gemm_tf32_kernel<0><<<dim3(3072 / 128, NROWS / 128), 256>>>(
        xn1, W_attn, b_attn, nullptr, qkv, NROWS, 3072, 1024);
    // 3) attention
    attn_kernel<<<dim3(T_SEQ / 64, BATCH * NHEAD), 256, attn_smem>>>(qkv, y);
    // 4) x1 = x + y @ W_proj + b_proj
    gemm_tf32_kernel<2><<<dim3(1024 / 128, NROWS / 128), 256>>>(
        y, W_proj, b_proj, x, x1, NROWS, 1024, 1024);
    // 5) ln2
    layernorm_kernel<<<NROWS, 256>>>(x1, ln2_g, ln2_b, xn2);
    // 6) h = gelu(xn2 @ W_fc + b_fc)
    gemm_tf32_kernel<1><<<dim3(4096 / 128, NROWS / 128), 256>>>(
        xn2, W_fc, b_fc, nullptr, hb, NROWS, 4096, 1024);
    // 7) out = x1 + h @ W_fc2 + b_fc2
    gemm_tf32_kernel<2><<<dim3(1024 / 128, NROWS / 128), 256>>>(
        hb, W_fc2, b_fc2, x1, out, NROWS, 1024, 4096);
}

// round 4
// speedup vs baseline: 3.1955x; 1.4381x over previous
#include <cuda_runtime.h>
#include <cstdint>
#include <cstddef>

#define N_EMBD 1024
#define T_SEQ  2048
#define BATCH  2
#define NROWS  (BATCH * T_SEQ)      // 4096
#define NHEAD  16
#define HDIM   64
#define EPS_LN 1e-5f

// ---------------- scratch (device globals; no allocations allowed) -------------
__device__ float g_xn1[(size_t)NROWS * N_EMBD];
__device__ float g_qkv[(size_t)NROWS * 3 * N_EMBD];
__device__ float g_y  [(size_t)NROWS * N_EMBD];
__device__ float g_x1 [(size_t)NROWS * N_EMBD];
__device__ float g_xn2[(size_t)NROWS * N_EMBD];
__device__ float g_h  [(size_t)NROWS * 4 * N_EMBD];

__device__ __forceinline__ uint32_t f2tf32(float f) {
    uint32_t u;
    asm("cvt.rn.tf32.f32 %0, %1;" : "=r"(u) : "f"(f));
    return u;
}
__device__ __forceinline__ float tf32f(float f) {
    return __uint_as_float(f2tf32(f));
}

__device__ __forceinline__ void mma_tf32(float* c, const uint32_t* a,
                                         uint32_t b0, uint32_t b1) {
    asm volatile(
        "mma.sync.aligned.m16n8k8.row.col.f32.tf32.tf32.f32 "
        "{%0,%1,%2,%3}, {%4,%5,%6,%7}, {%8,%9}, {%0,%1,%2,%3};"
        : "+f"(c[0]), "+f"(c[1]), "+f"(c[2]), "+f"(c[3])
        : "r"(a[0]), "r"(a[1]), "r"(a[2]), "r"(a[3]), "r"(b0), "r"(b1));
}

// ---------------- LayerNorm: one block per row of 1024 ------------------------
__global__ void layernorm_kernel(const float* __restrict__ x,
                                 const float* __restrict__ g,
                                 const float* __restrict__ b,
                                 float* __restrict__ out) {
    __shared__ float sh[8];
    __shared__ float stats[2];
    int row = blockIdx.x;
    int tid = threadIdx.x;                // 256 threads, 4 floats each
    const float4* xr = (const float4*)(x + (size_t)row * N_EMBD);
    float4 v = xr[tid];
    float s = v.x + v.y + v.z + v.w;
    #pragma unroll
    for (int o = 16; o > 0; o >>= 1) s += __shfl_xor_sync(0xffffffffu, s, o);
    if ((tid & 31) == 0) sh[tid >> 5] = s;
    __syncthreads();
    if (tid == 0) {
        float t = 0.f;
        #pragma unroll
        for (int i = 0; i < 8; i++) t += sh[i];
        stats[0] = t * (1.0f / N_EMBD);
    }
    __syncthreads();
    float mu = stats[0];
    float dx = v.x - mu, dy = v.y - mu, dz = v.z - mu, dw = v.w - mu;
    float ss = dx * dx + dy * dy + dz * dz + dw * dw;
    #pragma unroll
    for (int o = 16; o > 0; o >>= 1) ss += __shfl_xor_sync(0xffffffffu, ss, o);
    if ((tid & 31) == 0) sh[tid >> 5] = ss;
    __syncthreads();
    if (tid == 0) {
        float t = 0.f;
        #pragma unroll
        for (int i = 0; i < 8; i++) t += sh[i];
        stats[1] = rsqrtf(t * (1.0f / N_EMBD) + EPS_LN);
    }
    __syncthreads();
    float rstd = stats[1];
    int c = tid * 4;
    float4 gv = *(const float4*)(g + c);
    float4 bv = *(const float4*)(b + c);
    float4 o4;
    o4.x = dx * rstd * gv.x + bv.x;
    o4.y = dy * rstd * gv.y + bv.y;
    o4.z = dz * rstd * gv.z + bv.z;
    o4.w = dw * rstd * gv.w + bv.w;
    ((float4*)(out + (size_t)row * N_EMBD))[tid] = o4;
}

// ---------------- TF32 tensor-core GEMM (unchanged from R3) -------------------
#define AS_STRIDE 20
#define BS_STRIDE 136

template <int EPI>
__global__ __launch_bounds__(256, 2) void gemm_tf32_kernel(
    const float* __restrict__ A, const float* __restrict__ B,
    const float* __restrict__ bias, const float* __restrict__ res,
    float* __restrict__ C, int M, int N, int K) {
    __shared__ uint32_t As[2][128 * AS_STRIDE];
    __shared__ uint32_t Bs[2][16 * BS_STRIDE];

    const int tid = threadIdx.x;
    const int bx = blockIdx.x, by = blockIdx.y;
    const int warp = tid >> 5, lane = tid & 31;
    const int wm = warp >> 2, wn = warp & 3;
    const int group = lane >> 2, tig = lane & 3;

    const int a_row0 = tid >> 2;
    const int a_c    = (tid & 3) * 4;
    const int b_row0 = tid >> 5;
    const int b_c    = (tid & 31) * 4;

    const float* Ap0 = A + (size_t)(by * 128 + a_row0) * K + a_c;
    const float* Ap1 = Ap0 + (size_t)64 * K;
    const float* Bp0 = B + (size_t)b_row0 * N + bx * 128 + b_c;
    const float* Bp1 = Bp0 + (size_t)8 * N;

    float acc[4][4][4];
    #pragma unroll
    for (int mi = 0; mi < 4; mi++)
        #pragma unroll
        for (int ni = 0; ni < 4; ni++)
            #pragma unroll
            for (int r = 0; r < 4; r++) acc[mi][ni][r] = 0.f;

    const int nk = K / 16;

    {
        float4 a0 = *(const float4*)Ap0;
        float4 a1 = *(const float4*)Ap1;
        float4 b0 = *(const float4*)Bp0;
        float4 b1 = *(const float4*)Bp1;
        uint32_t* as = &As[0][0];
        uint32_t* bs = &Bs[0][0];
        as[(a_row0)      * AS_STRIDE + a_c + 0] = f2tf32(a0.x);
        as[(a_row0)      * AS_STRIDE + a_c + 1] = f2tf32(a0.y);
        as[(a_row0)      * AS_STRIDE + a_c + 2] = f2tf32(a0.z);
        as[(a_row0)      * AS_STRIDE + a_c + 3] = f2tf32(a0.w);
        as[(a_row0 + 64) * AS_STRIDE + a_c + 0] = f2tf32(a1.x);
        as[(a_row0 + 64) * AS_STRIDE + a_c + 1] = f2tf32(a1.y);
        as[(a_row0 + 64) * AS_STRIDE + a_c + 2] = f2tf32(a1.z);
        as[(a_row0 + 64) * AS_STRIDE + a_c + 3] = f2tf32(a1.w);
        bs[(b_row0)     * BS_STRIDE + b_c + 0] = f2tf32(b0.x);
        bs[(b_row0)     * BS_STRIDE + b_c + 1] = f2tf32(b0.y);
        bs[(b_row0)     * BS_STRIDE + b_c + 2] = f2tf32(b0.z);
        bs[(b_row0)     * BS_STRIDE + b_c + 3] = f2tf32(b0.w);
        bs[(b_row0 + 8) * BS_STRIDE + b_c + 0] = f2tf32(b1.x);
        bs[(b_row0 + 8) * BS_STRIDE + b_c + 1] = f2tf32(b1.y);
        bs[(b_row0 + 8) * BS_STRIDE + b_c + 2] = f2tf32(b1.z);
        bs[(b_row0 + 8) * BS_STRIDE + b_c + 3] = f2tf32(b1.w);
    }
    __syncthreads();

    for (int it = 0; it < nk; it++) {
        float4 pa0, pa1, pb0, pb1;
        const bool have_next = (it + 1 < nk);
        if (have_next) {
            const float* ap0 = Ap0 + (it + 1) * 16;
            const float* ap1 = Ap1 + (it + 1) * 16;
            const float* bp0 = Bp0 + (size_t)(it + 1) * 16 * N;
            const float* bp1 = Bp1 + (size_t)(it + 1) * 16 * N;
            pa0 = *(const float4*)ap0;
            pa1 = *(const float4*)ap1;
            pb0 = *(const float4*)bp0;
            pb1 = *(const float4*)bp1;
        }

        const uint32_t* as = &As[it & 1][0];
        const uint32_t* bs = &Bs[it & 1][0];
        #pragma unroll
        for (int ks = 0; ks < 2; ks++) {
            const int kb = ks * 8;
            uint32_t afr[4][4];
            #pragma unroll
            for (int mi = 0; mi < 4; mi++) {
                int rb = wm * 64 + mi * 16;
                afr[mi][0] = as[(rb + group)     * AS_STRIDE + kb + tig];
                afr[mi][1] = as[(rb + group + 8) * AS_STRIDE + kb + tig];
                afr[mi][2] = as[(rb + group)     * AS_STRIDE + kb + tig + 4];
                afr[mi][3] = as[(rb + group + 8) * AS_STRIDE + kb + tig + 4];
            }
            uint32_t bfr[4][2];
            #pragma unroll
            for (int ni = 0; ni < 4; ni++) {
                int cb = wn * 32 + ni * 8;
                bfr[ni][0] = bs[(kb + tig)     * BS_STRIDE + cb + group];
                bfr[ni][1] = bs[(kb + tig + 4) * BS_STRIDE + cb + group];
            }
            #pragma unroll
            for (int mi = 0; mi < 4; mi++)
                #pragma unroll
                for (int ni = 0; ni < 4; ni++)
                    mma_tf32(acc[mi][ni], afr[mi], bfr[ni][0], bfr[ni][1]);
        }

        if (have_next) {
            uint32_t* asn = &As[(it + 1) & 1][0];
            uint32_t* bsn = &Bs[(it + 1) & 1][0];
            asn[(a_row0)      * AS_STRIDE + a_c + 0] = f2tf32(pa0.x);
            asn[(a_row0)      * AS_STRIDE + a_c + 1] = f2tf32(pa0.y);
            asn[(a_row0)      * AS_STRIDE + a_c + 2] = f2tf32(pa0.z);
            asn[(a_row0)      * AS_STRIDE + a_c + 3] = f2tf32(pa0.w);
            asn[(a_row0 + 64) * AS_STRIDE + a_c + 0] = f2tf32(pa1.x);
            asn[(a_row0 + 64) * AS_STRIDE + a_c + 1] = f2tf32(pa1.y);
            asn[(a_row0 + 64) * AS_STRIDE + a_c + 2] = f2tf32(pa1.z);
            asn[(a_row0 + 64) * AS_STRIDE + a_c + 3] = f2tf32(pa1.w);
            bsn[(b_row0)     * BS_STRIDE + b_c + 0] = f2tf32(pb0.x);
            bsn[(b_row0)     * BS_STRIDE + b_c + 1] = f2tf32(pb0.y);
            bsn[(b_row0)     * BS_STRIDE + b_c + 2] = f2tf32(pb0.z);
            bsn[(b_row0)     * BS_STRIDE + b_c + 3] = f2tf32(pb0.w);
            bsn[(b_row0 + 8) * BS_STRIDE + b_c + 0] = f2tf32(pb1.x);
            bsn[(b_row0 + 8) * BS_STRIDE + b_c + 1] = f2tf32(pb1.y);
            bsn[(b_row0 + 8) * BS_STRIDE + b_c + 2] = f2tf32(pb1.z);
            bsn[(b_row0 + 8) * BS_STRIDE + b_c + 3] = f2tf32(pb1.w);
        }
        __syncthreads();
    }

    #pragma unroll
    for (int ni = 0; ni < 4; ni++) {
        int col = bx * 128 + wn * 32 + ni * 8 + 2 * tig;
        float bi0 = bias[col], bi1 = bias[col + 1];
        #pragma unroll
        for (int mi = 0; mi < 4; mi++) {
            int row = by * 128 + wm * 64 + mi * 16 + group;
            #pragma unroll
            for (int h = 0; h < 2; h++) {
                int r = row + h * 8;
                float v0 = acc[mi][ni][2 * h + 0] + bi0;
                float v1 = acc[mi][ni][2 * h + 1] + bi1;
                if (EPI == 1) {
                    v0 = v0 * 0.5f * (1.0f + erff(v0 * 0.70710678118654752f));
                    v1 = v1 * 0.5f * (1.0f + erff(v1 * 0.70710678118654752f));
                }
                if (EPI == 2) {
                    const float* rr = res + (size_t)r * N + col;
                    v0 += rr[0];
                    v1 += rr[1];
                }
                float2* cp = (float2*)(C + (size_t)r * N + col);
                *cp = make_float2(v0, v1);
            }
        }
    }
}

// ---------------- Flash attention, TF32 tensor cores ---------------------------
// BQ=128 q-rows/block, BK=64 keys/tile. 8 warps x 16 q-rows. Q frags in regs.
// Qs region reused as Ps after fragment extraction.
#define AT_STR 68
#define ATT_SMEM_FLOATS ((128 + 64 + 64) * AT_STR)

__global__ __launch_bounds__(256, 2) void attn_mma_kernel(
    const float* __restrict__ qkv, float* __restrict__ y) {
    extern __shared__ float smem[];
    float* Qs = smem;                        // [128][AT_STR], reused as Ps
    float* Ks = smem + 128 * AT_STR;         // [64 key][AT_STR] (d along row)
    float* Vt = Ks + 64 * AT_STR;            // [64 d][AT_STR]   (key along row)

    const int qt = blockIdx.x;               // 0..15  (128 rows each)
    const int bh = blockIdx.y;
    const int b = bh >> 4, h = bh & 15;
    const int tid = threadIdx.x;
    const int warp = tid >> 5, lane = tid & 31;
    const int g = lane >> 2, tig = lane & 3;
    const int rq = warp * 16;
    const int C3 = 3 * N_EMBD;
    const float* base = qkv + (size_t)b * T_SEQ * C3 + h * HDIM;

    // ---- load Q tile (128 x 64), scaled by 1/8, tf32-converted ----
    #pragma unroll
    for (int i = 0; i < 8; i++) {
        int fi = tid + i * 256;              // 2048 float4 units
        int row = fi >> 4, c4 = (fi & 15) * 4;
        float4 v = *(const float4*)(base + (size_t)(qt * 128 + row) * C3 + c4);
        *(float4*)&Qs[row * AT_STR + c4] =
            make_float4(tf32f(v.x * 0.125f), tf32f(v.y * 0.125f),
                        tf32f(v.z * 0.125f), tf32f(v.w * 0.125f));
    }
    __syncthreads();

    // ---- extract Q fragments into registers (held for whole KV loop) ----
    uint32_t qf[8][4];
    #pragma unroll
    for (int kb8 = 0; kb8 < 8; kb8++) {
        int kb = kb8 * 8;
        qf[kb8][0] = __float_as_uint(Qs[(rq + g)     * AT_STR + kb + tig]);
        qf[kb8][1] = __float_as_uint(Qs[(rq + g + 8) * AT_STR + kb + tig]);
        qf[kb8][2] = __float_as_uint(Qs[(rq + g)     * AT_STR + kb + tig + 4]);
        qf[kb8][3] = __float_as_uint(Qs[(rq + g + 8) * AT_STR + kb + tig + 4]);
    }
    __syncthreads();   // all warps done reading Qs before it becomes Ps

    float m0 = -1e30f, m1 = -1e30f, l0 = 0.f, l1 = 0.f;
    float acc[8][4];
    #pragma unroll
    for (int ni = 0; ni < 8; ni++)
        #pragma unroll
        for (int r = 0; r < 4; r++) acc[ni][r] = 0.f;

    const int ktmax = 2 * qt + 1;
    for (int kt = 0; kt <= ktmax; kt++) {
        __syncthreads();   // prior iter's Ks/Vt/Ps reads complete
        // ---- load K (64x64, tf32) and V^T (transpose, tf32) ----
        #pragma unroll
        for (int i = 0; i < 4; i++) {
            int fi = tid + i * 256;          // 1024 float4 units
            int key = fi >> 4, c4 = (fi & 15) * 4;
            const float* kp = base + (size_t)(kt * 64 + key) * C3 + N_EMBD + c4;
            float4 kv = *(const float4*)kp;
            float4 vv = *(const float4*)(kp + N_EMBD);
            *(float4*)&Ks[key * AT_STR + c4] =
                make_float4(tf32f(kv.x), tf32f(kv.y), tf32f(kv.z), tf32f(kv.w));
            Vt[(c4 + 0) * AT_STR + key] = tf32f(vv.x);
            Vt[(c4 + 1) * AT_STR + key] = tf32f(vv.y);
            Vt[(c4 + 2) * AT_STR + key] = tf32f(vv.z);
            Vt[(c4 + 3) * AT_STR + key] = tf32f(vv.w);
        }
        __syncthreads();

        // ---- S = (Q/8) K^T : 8 n-tiles (keys) x 8 k-steps (d) ----
        float s[8][4];
        #pragma unroll
        for (int ni = 0; ni < 8; ni++)
            #pragma unroll
            for (int r = 0; r < 4; r++) s[ni][r] = 0.f;
        #pragma unroll
        for (int kb8 = 0; kb8 < 8; kb8++) {
            int kb = kb8 * 8;
            #pragma unroll
            for (int ni = 0; ni < 8; ni++) {
                int cb = ni * 8;
                uint32_t b0 = __float_as_uint(Ks[(cb + g) * AT_STR + kb + tig]);
                uint32_t b1 = __float_as_uint(Ks[(cb + g) * AT_STR + kb + tig + 4]);
                mma_tf32(s[ni], qf[kb8], b0, b1);
            }
        }

        // ---- causal mask (only tiles straddling the diagonal) ----
        if (kt >= 2 * qt) {
            int qg0 = qt * 128 + rq + g;
            int qg1 = qg0 + 8;
            #pragma unroll
            for (int ni = 0; ni < 8; ni++) {
                int kg0 = kt * 64 + ni * 8 + tig * 2;
                if (kg0 > qg0)     s[ni][0] = -1e30f;
                if (kg0 + 1 > qg0) s[ni][1] = -1e30f;
                if (kg0 > qg1)     s[ni][2] = -1e30f;
                if (kg0 + 1 > qg1) s[ni][3] = -1e30f;
            }
        }

        // ---- online softmax on fragment layout ----
        float mx0 = -1e30f, mx1 = -1e30f;
        #pragma unroll
        for (int ni = 0; ni < 8; ni++) {
            mx0 = fmaxf(mx0, fmaxf(s[ni][0], s[ni][1]));
            mx1 = fmaxf(mx1, fmaxf(s[ni][2], s[ni][3]));
        }
        #pragma unroll
        for (int o = 1; o < 4; o <<= 1) {
            mx0 = fmaxf(mx0, __shfl_xor_sync(0xffffffffu, mx0, o));
            mx1 = fmaxf(mx1, __shfl_xor_sync(0xffffffffu, mx1, o));
        }
        float mn0 = fmaxf(m0, mx0), mn1 = fmaxf(m1, mx1);
        float corr0 = __expf(m0 - mn0), corr1 = __expf(m1 - mn1);
        m0 = mn0; m1 = mn1;
        float ls0 = 0.f, ls1 = 0.f;
        #pragma unroll
        for (int ni = 0; ni < 8; ni++) {
            s[ni][0] = __expf(s[ni][0] - mn0);
            s[ni][1] = __expf(s[ni][1] - mn0);
            s[ni][2] = __expf(s[ni][2] - mn1);
            s[ni][3] = __expf(s[ni][3] - mn1);
            ls0 += s[ni][0] + s[ni][1];
            ls1 += s[ni][2] + s[ni][3];
        }
        #pragma unroll
        for (int o = 1; o < 4; o <<= 1) {
            ls0 += __shfl_xor_sync(0xffffffffu, ls0, o);
            ls1 += __shfl_xor_sync(0xffffffffu, ls1, o);
        }
        l0 = l0 * corr0 + ls0;
        l1 = l1 * corr1 + ls1;
        #pragma unroll
        for (int ni = 0; ni < 8; ni++) {
            acc[ni][0] *= corr0; acc[ni][1] *= corr0;
            acc[ni][2] *= corr1; acc[ni][3] *= corr1;
        }

        // ---- publish P (tf32) into Ps (= Qs region) ----
        #pragma unroll
        for (int ni = 0; ni < 8; ni++) {
            int cb = ni * 8 + tig * 2;
            *(float2*)&Qs[(rq + g)     * AT_STR + cb] =
                make_float2(tf32f(s[ni][0]), tf32f(s[ni][1]));
            *(float2*)&Qs[(rq + g + 8) * AT_STR + cb] =
                make_float2(tf32f(s[ni][2]), tf32f(s[ni][3]));
        }
        __syncthreads();

        // ---- acc += P @ V : k-steps over keys, n-tiles over d ----
        #pragma unroll
        for (int kb8 = 0; kb8 < 8; kb8++) {
            int kb = kb8 * 8;
            uint32_t pa[4];
            pa[0] = __float_as_uint(Qs[(rq + g)     * AT_STR + kb + tig]);
            pa[1] = __float_as_uint(Qs[(rq + g + 8) * AT_STR + kb + tig]);
            pa[2] = __float_as_uint(Qs[(rq + g)     * AT_STR + kb + tig + 4]);
            pa[3] = __float_as_uint(Qs[(rq + g + 8) * AT_STR + kb + tig + 4]);
            #pragma unroll
            for (int ni = 0; ni < 8; ni++) {
                uint32_t b0 = __float_as_uint(Vt[(ni * 8 + g) * AT_STR + kb + tig]);
                uint32_t b1 = __float_as_uint(Vt[(ni * 8 + g) * AT_STR + kb + tig + 4]);
                mma_tf32(acc[ni], pa, b0, b1);
            }
        }
    }

    // ---- write O = acc / l ----
    float inv0 = 1.0f / l0, inv1 = 1.0f / l1;
    int row0 = b * T_SEQ + qt * 128 + rq + g;
    #pragma unroll
    for (int ni = 0; ni < 8; ni++) {
        int col = h * HDIM + ni * 8 + tig * 2;
        *(float2*)&y[(size_t)row0 * N_EMBD + col] =
            make_float2(acc[ni][0] * inv0, acc[ni][1] * inv0);
        *(float2*)&y[(size_t)(row0 + 8) * N_EMBD + col] =
            make_float2(acc[ni][2] * inv1, acc[ni][3] * inv1);
    }
}

// ---------------------------------- launcher -----------------------------------
extern "C" void kernel_launch(void* const* d_in, const int* in_sizes, int n_in,
                              void* d_out, int out_size) {
    const float* x      = (const float*)d_in[0];
    const float* ln1_g  = (const float*)d_in[1];
    const float* ln1_b  = (const float*)d_in[2];
    const float* W_attn = (const float*)d_in[3];
    const float* b_attn = (const float*)d_in[4];
    const float* W_proj = (const float*)d_in[5];
    const float* b_proj = (const float*)d_in[6];
    const float* ln2_g  = (const float*)d_in[7];
    const float* ln2_b  = (const float*)d_in[8];
    const float* W_fc   = (const float*)d_in[9];
    const float* b_fc   = (const float*)d_in[10];
    const float* W_fc2  = (const float*)d_in[11];
    const float* b_fc2  = (const float*)d_in[12];
    float* out = (float*)d_out;

    float *xn1, *qkv, *y, *x1, *xn2, *hb;
    cudaGetSymbolAddress((void**)&xn1, g_xn1);
    cudaGetSymbolAddress((void**)&qkv, g_qkv);
    cudaGetSymbolAddress((void**)&y,   g_y);
    cudaGetSymbolAddress((void**)&x1,  g_x1);
    cudaGetSymbolAddress((void**)&xn2, g_xn2);
    cudaGetSymbolAddress((void**)&hb,  g_h);

    const int attn_smem = ATT_SMEM_FLOATS * (int)sizeof(float);  // 69632 B
    cudaFuncSetAttribute(attn_mma_kernel,
                         cudaFuncAttributeMaxDynamicSharedMemorySize, attn_smem);

    // 1) ln1
    layernorm_kernel<<<NROWS, 256>>>(x, ln1_g, ln1_b, xn1);
    // 2) qkv = xn1 @ W_attn + b_attn
    gemm_tf32_kernel<0><<<dim3(3072 / 128, NROWS / 128), 256>>>(
        xn1, W_attn, b_attn, nullptr, qkv, NROWS, 3072, 1024);
    // 3) attention (tensor cores)
    attn_mma_kernel<<<dim3(T_SEQ / 128, BATCH * NHEAD), 256, attn_smem>>>(qkv, y);
    // 4) x1 = x + y @ W_proj + b_proj
    gemm_tf32_kernel<2><<<dim3(1024 / 128, NROWS / 128), 256>>>(
        y, W_proj, b_proj, x, x1, NROWS, 1024, 1024);
    // 5) ln2
    layernorm_kernel<<<NROWS, 256>>>(x1, ln2_g, ln2_b, xn2);
    // 6) h = gelu(xn2 @ W_fc + b_fc)
    gemm_tf32_kernel<1><<<dim3(4096 / 128, NROWS / 128), 256>>>(
        xn2, W_fc, b_fc, nullptr, hb, NROWS, 4096, 1024);
    // 7) out = x1 + h @ W_fc2 + b_fc2
    gemm_tf32_kernel<2><<<dim3(1024 / 128, NROWS / 128), 256>>>(
        hb, W_fc2, b_fc2, x1, out, NROWS, 1024, 4096);
}

// round 5
// speedup vs baseline: 3.3661x; 1.0534x over previous
#include <cuda_runtime.h>
#include <cstdint>
#include <cstddef>

#define N_EMBD 1024
#define T_SEQ  2048
#define BATCH  2
#define NROWS  (BATCH * T_SEQ)      // 4096
#define NHEAD  16
#define HDIM   64
#define EPS_LN 1e-5f

// ---------------- scratch (device globals; no allocations allowed) -------------
__device__ float g_xn1[(size_t)NROWS * N_EMBD];
__device__ float g_qkv[(size_t)NROWS * 3 * N_EMBD];
__device__ float g_y  [(size_t)NROWS * N_EMBD];
__device__ float g_x1 [(size_t)NROWS * N_EMBD];
__device__ float g_xn2[(size_t)NROWS * N_EMBD];
__device__ float g_h  [(size_t)NROWS * 4 * N_EMBD];

__device__ __forceinline__ uint32_t f2tf32(float f) {
    uint32_t u;
    asm("cvt.rn.tf32.f32 %0, %1;" : "=r"(u) : "f"(f));
    return u;
}
__device__ __forceinline__ float tf32f(float f) {
    return __uint_as_float(f2tf32(f));
}

__device__ __forceinline__ void mma_tf32(float* c, const uint32_t* a,
                                         uint32_t b0, uint32_t b1) {
    asm volatile(
        "mma.sync.aligned.m16n8k8.row.col.f32.tf32.tf32.f32 "
        "{%0,%1,%2,%3}, {%4,%5,%6,%7}, {%8,%9}, {%0,%1,%2,%3};"
        : "+f"(c[0]), "+f"(c[1]), "+f"(c[2]), "+f"(c[3])
        : "r"(a[0]), "r"(a[1]), "r"(a[2]), "r"(a[3]), "r"(b0), "r"(b1));
}

// ---------------- LayerNorm: one block per row of 1024 ------------------------
__global__ void layernorm_kernel(const float* __restrict__ x,
                                 const float* __restrict__ g,
                                 const float* __restrict__ b,
                                 float* __restrict__ out) {
    __shared__ float sh[8];
    __shared__ float stats[2];
    int row = blockIdx.x;
    int tid = threadIdx.x;
    const float4* xr = (const float4*)(x + (size_t)row * N_EMBD);
    float4 v = xr[tid];
    float s = v.x + v.y + v.z + v.w;
    #pragma unroll
    for (int o = 16; o > 0; o >>= 1) s += __shfl_xor_sync(0xffffffffu, s, o);
    if ((tid & 31) == 0) sh[tid >> 5] = s;
    __syncthreads();
    if (tid == 0) {
        float t = 0.f;
        #pragma unroll
        for (int i = 0; i < 8; i++) t += sh[i];
        stats[0] = t * (1.0f / N_EMBD);
    }
    __syncthreads();
    float mu = stats[0];
    float dx = v.x - mu, dy = v.y - mu, dz = v.z - mu, dw = v.w - mu;
    float ss = dx * dx + dy * dy + dz * dz + dw * dw;
    #pragma unroll
    for (int o = 16; o > 0; o >>= 1) ss += __shfl_xor_sync(0xffffffffu, ss, o);
    if ((tid & 31) == 0) sh[tid >> 5] = ss;
    __syncthreads();
    if (tid == 0) {
        float t = 0.f;
        #pragma unroll
        for (int i = 0; i < 8; i++) t += sh[i];
        stats[1] = rsqrtf(t * (1.0f / N_EMBD) + EPS_LN);
    }
    __syncthreads();
    float rstd = stats[1];
    int c = tid * 4;
    float4 gv = *(const float4*)(g + c);
    float4 bv = *(const float4*)(b + c);
    float4 o4;
    o4.x = dx * rstd * gv.x + bv.x;
    o4.y = dy * rstd * gv.y + bv.y;
    o4.z = dz * rstd * gv.z + bv.z;
    o4.w = dw * rstd * gv.w + bv.w;
    ((float4*)(out + (size_t)row * N_EMBD))[tid] = o4;
}

// ---------------- TF32 tensor-core GEMM, fragment-packed smem ------------------
// BM=128, BN=128, BK=16; 8 warps (2Mx4N); warp tile 64x32; mma.m16n8k8 tf32.
// A smem: [mt(8) x ks(2)] tiles of 128 words: [g(8)][rot(t)(4)][slot(4)]
//   slot: 0=(g,t) 1=(g+8,t) 2=(g,t+4) 3=(g+8,t+4), rot=(t+g+(g>>2))&3
//   -> one LDS.128 per A fragment.
// B smem: [nt(16) x ks(2)] tiles of 66-word stride: [g(8)][t(4)*2 + u]
//   u: 0=B[k=t][n=g], 1=B[k=t+4][n=g]  -> one LDS.64 per B fragment.
#define A_TILE_W 128
#define B_TILE_W 66

template <int EPI>
__global__ __launch_bounds__(256, 2) void gemm_tf32_kernel(
    const float* __restrict__ A, const float* __restrict__ B,
    const float* __restrict__ bias, const float* __restrict__ res,
    float* __restrict__ C, int M, int N, int K) {
    __shared__ uint32_t As[2][16 * A_TILE_W];   // 2048 words / buf
    __shared__ uint32_t Bs[2][32 * B_TILE_W];   // 2112 words / buf

    const int tid = threadIdx.x;
    const int bx = blockIdx.x, by = blockIdx.y;
    const int warp = tid >> 5, lane = tid & 31;
    const int wm = warp >> 2, wn = warp & 3;
    const int lg = lane >> 2, lt = lane & 3;

    // ---- staging indices ----
    // A: thread loads rows (tid>>2) and +64, 4 consecutive k at (tid&3)*4
    const int arow = tid >> 2;
    const int ac   = (tid & 3) * 4;
    const int amt = arow >> 4, ahi = (arow >> 3) & 1, ag = arow & 7;
    const int aks = ac >> 3, ahj = (ac >> 2) & 1;
    const int aslot = 2 * ahj + ahi;
    const int abase0 = (amt * 2 + aks) * A_TILE_W + ag * 16 + aslot;
    const int abase1 = abase0 + 8 * A_TILE_W;   // rows +64 -> mt+4
    // B: thread loads k = tid>>4, cols (tid&15)*4 and +64 (coalesced rows)
    const int bk = tid >> 4;
    const int bc = (tid & 15) * 4;
    const int bks = bk >> 3, bt = bk & 3, bu = (bk >> 2) & 1;
    const int bnt = bc >> 3, bg = bc & 7;
    const int bbase0 = (bnt * 2 + bks) * B_TILE_W + bg * 8 + bt * 2 + bu;
    const int bbase1 = bbase0 + 16 * B_TILE_W;  // cols +64 -> nt+8

    const float* Ap0 = A + (size_t)(by * 128 + arow) * K + ac;
    const float* Ap1 = Ap0 + (size_t)64 * K;
    const float* Bp0 = B + (size_t)bk * N + bx * 128 + bc;
    const float* Bp1 = Bp0 + 64;

    // ---- fragment-load offsets (per lane, constant) ----
    const int aoff = lg * 16 + ((lt + lg + (lg >> 2)) & 3) * 4;
    const int boff = lg * 8 + lt * 2;

    float acc[4][4][4];
    #pragma unroll
    for (int mi = 0; mi < 4; mi++)
        #pragma unroll
        for (int ni = 0; ni < 4; ni++)
            #pragma unroll
            for (int r = 0; r < 4; r++) acc[mi][ni][r] = 0.f;

    const int nk = K / 16;

    // store helpers
    #define STORE_A(dst, base, v)                                         \
        do {                                                              \
            (dst)[(base) + (((0 + ag + (ag >> 2)) & 3) << 2)] = f2tf32((v).x); \
            (dst)[(base) + (((1 + ag + (ag >> 2)) & 3) << 2)] = f2tf32((v).y); \
            (dst)[(base) + (((2 + ag + (ag >> 2)) & 3) << 2)] = f2tf32((v).z); \
            (dst)[(base) + (((3 + ag + (ag >> 2)) & 3) << 2)] = f2tf32((v).w); \
        } while (0)
    #define STORE_B(dst, base, v)                                         \
        do {                                                              \
            (dst)[(base) + 0]  = f2tf32((v).x);                           \
            (dst)[(base) + 8]  = f2tf32((v).y);                           \
            (dst)[(base) + 16] = f2tf32((v).z);                           \
            (dst)[(base) + 24] = f2tf32((v).w);                           \
        } while (0)

    // prologue: tile 0 -> buf 0
    {
        float4 a0 = *(const float4*)Ap0;
        float4 a1 = *(const float4*)Ap1;
        float4 b0 = *(const float4*)Bp0;
        float4 b1 = *(const float4*)Bp1;
        STORE_A(As[0], abase0, a0);
        STORE_A(As[0], abase1, a1);
        STORE_B(Bs[0], bbase0, b0);
        STORE_B(Bs[0], bbase1, b1);
    }
    __syncthreads();

    for (int it = 0; it < nk; it++) {
        float4 pa0, pa1, pb0, pb1;
        const bool have_next = (it + 1 < nk);
        if (have_next) {
            pa0 = *(const float4*)(Ap0 + (it + 1) * 16);
            pa1 = *(const float4*)(Ap1 + (it + 1) * 16);
            pb0 = *(const float4*)(Bp0 + (size_t)(it + 1) * 16 * N);
            pb1 = *(const float4*)(Bp1 + (size_t)(it + 1) * 16 * N);
        }

        const uint32_t* as = As[it & 1];
        const uint32_t* bs = Bs[it & 1];
        #pragma unroll
        for (int ks = 0; ks < 2; ks++) {
            uint4 af[4];
            uint2 bf[4];
            #pragma unroll
            for (int mi = 0; mi < 4; mi++)
                af[mi] = *(const uint4*)&as[((wm * 4 + mi) * 2 + ks) * A_TILE_W + aoff];
            #pragma unroll
            for (int ni = 0; ni < 4; ni++)
                bf[ni] = *(const uint2*)&bs[((wn * 4 + ni) * 2 + ks) * B_TILE_W + boff];
            #pragma unroll
            for (int mi = 0; mi < 4; mi++)
                #pragma unroll
                for (int ni = 0; ni < 4; ni++)
                    mma_tf32(acc[mi][ni], (const uint32_t*)&af[mi],
                             bf[ni].x, bf[ni].y);
        }

        if (have_next) {
            uint32_t* asn = As[(it + 1) & 1];
            uint32_t* bsn = Bs[(it + 1) & 1];
            STORE_A(asn, abase0, pa0);
            STORE_A(asn, abase1, pa1);
            STORE_B(bsn, bbase0, pb0);
            STORE_B(bsn, bbase1, pb1);
        }
        __syncthreads();
    }
    #undef STORE_A
    #undef STORE_B

    // epilogue (acc layout unchanged)
    #pragma unroll
    for (int ni = 0; ni < 4; ni++) {
        int col = bx * 128 + wn * 32 + ni * 8 + 2 * lt;
        float bi0 = bias[col], bi1 = bias[col + 1];
        #pragma unroll
        for (int mi = 0; mi < 4; mi++) {
            int row = by * 128 + wm * 64 + mi * 16 + lg;
            #pragma unroll
            for (int h = 0; h < 2; h++) {
                int r = row + h * 8;
                float v0 = acc[mi][ni][2 * h + 0] + bi0;
                float v1 = acc[mi][ni][2 * h + 1] + bi1;
                if (EPI == 1) {
                    v0 = v0 * 0.5f * (1.0f + erff(v0 * 0.70710678118654752f));
                    v1 = v1 * 0.5f * (1.0f + erff(v1 * 0.70710678118654752f));
                }
                if (EPI == 2) {
                    const float* rr = res + (size_t)r * N + col;
                    v0 += rr[0];
                    v1 += rr[1];
                }
                float2* cp = (float2*)(C + (size_t)r * N + col);
                *cp = make_float2(v0, v1);
            }
        }
    }
}

// ---------------- Flash attention, TF32 tensor cores (unchanged R4) ------------
#define AT_STR 68
#define ATT_SMEM_FLOATS ((128 + 64 + 64) * AT_STR)

__global__ __launch_bounds__(256, 2) void attn_mma_kernel(
    const float* __restrict__ qkv, float* __restrict__ y) {
    extern __shared__ float smem[];
    float* Qs = smem;                        // [128][AT_STR], reused as Ps
    float* Ks = smem + 128 * AT_STR;
    float* Vt = Ks + 64 * AT_STR;

    const int qt = blockIdx.x;
    const int bh = blockIdx.y;
    const int b = bh >> 4, h = bh & 15;
    const int tid = threadIdx.x;
    const int warp = tid >> 5, lane = tid & 31;
    const int g = lane >> 2, tig = lane & 3;
    const int rq = warp * 16;
    const int C3 = 3 * N_EMBD;
    const float* base = qkv + (size_t)b * T_SEQ * C3 + h * HDIM;

    #pragma unroll
    for (int i = 0; i < 8; i++) {
        int fi = tid + i * 256;
        int row = fi >> 4, c4 = (fi & 15) * 4;
        float4 v = *(const float4*)(base + (size_t)(qt * 128 + row) * C3 + c4);
        *(float4*)&Qs[row * AT_STR + c4] =
            make_float4(tf32f(v.x * 0.125f), tf32f(v.y * 0.125f),
                        tf32f(v.z * 0.125f), tf32f(v.w * 0.125f));
    }
    __syncthreads();

    uint32_t qf[8][4];
    #pragma unroll
    for (int kb8 = 0; kb8 < 8; kb8++) {
        int kb = kb8 * 8;
        qf[kb8][0] = __float_as_uint(Qs[(rq + g)     * AT_STR + kb + tig]);
        qf[kb8][1] = __float_as_uint(Qs[(rq + g + 8) * AT_STR + kb + tig]);
        qf[kb8][2] = __float_as_uint(Qs[(rq + g)     * AT_STR + kb + tig + 4]);
        qf[kb8][3] = __float_as_uint(Qs[(rq + g + 8) * AT_STR + kb + tig + 4]);
    }
    __syncthreads();

    float m0 = -1e30f, m1 = -1e30f, l0 = 0.f, l1 = 0.f;
    float acc[8][4];
    #pragma unroll
    for (int ni = 0; ni < 8; ni++)
        #pragma unroll
        for (int r = 0; r < 4; r++) acc[ni][r] = 0.f;

    const int ktmax = 2 * qt + 1;
    for (int kt = 0; kt <= ktmax; kt++) {
        __syncthreads();
        #pragma unroll
        for (int i = 0; i < 4; i++) {
            int fi = tid + i * 256;
            int key = fi >> 4, c4 = (fi & 15) * 4;
            const float* kp = base + (size_t)(kt * 64 + key) * C3 + N_EMBD + c4;
            float4 kv = *(const float4*)kp;
            float4 vv = *(const float4*)(kp + N_EMBD);
            *(float4*)&Ks[key * AT_STR + c4] =
                make_float4(tf32f(kv.x), tf32f(kv.y), tf32f(kv.z), tf32f(kv.w));
            Vt[(c4 + 0) * AT_STR + key] = tf32f(vv.x);
            Vt[(c4 + 1) * AT_STR + key] = tf32f(vv.y);
            Vt[(c4 + 2) * AT_STR + key] = tf32f(vv.z);
            Vt[(c4 + 3) * AT_STR + key] = tf32f(vv.w);
        }
        __syncthreads();

        float s[8][4];
        #pragma unroll
        for (int ni = 0; ni < 8; ni++)
            #pragma unroll
            for (int r = 0; r < 4; r++) s[ni][r] = 0.f;
        #pragma unroll
        for (int kb8 = 0; kb8 < 8; kb8++) {
            int kb = kb8 * 8;
            #pragma unroll
            for (int ni = 0; ni < 8; ni++) {
                int cb = ni * 8;
                uint32_t b0 = __float_as_uint(Ks[(cb + g) * AT_STR + kb + tig]);
                uint32_t b1 = __float_as_uint(Ks[(cb + g) * AT_STR + kb + tig + 4]);
                mma_tf32(s[ni], qf[kb8], b0, b1);
            }
        }

        if (kt >= 2 * qt) {
            int qg0 = qt * 128 + rq + g;
            int qg1 = qg0 + 8;
            #pragma unroll
            for (int ni = 0; ni < 8; ni++) {
                int kg0 = kt * 64 + ni * 8 + tig * 2;
                if (kg0 > qg0)     s[ni][0] = -1e30f;
                if (kg0 + 1 > qg0) s[ni][1] = -1e30f;
                if (kg0 > qg1)     s[ni][2] = -1e30f;
                if (kg0 + 1 > qg1) s[ni][3] = -1e30f;
            }
        }

        float mx0 = -1e30f, mx1 = -1e30f;
        #pragma unroll
        for (int ni = 0; ni < 8; ni++) {
            mx0 = fmaxf(mx0, fmaxf(s[ni][0], s[ni][1]));
            mx1 = fmaxf(mx1, fmaxf(s[ni][2], s[ni][3]));
        }
        #pragma unroll
        for (int o = 1; o < 4; o <<= 1) {
            mx0 = fmaxf(mx0, __shfl_xor_sync(0xffffffffu, mx0, o));
            mx1 = fmaxf(mx1, __shfl_xor_sync(0xffffffffu, mx1, o));
        }
        float mn0 = fmaxf(m0, mx0), mn1 = fmaxf(m1, mx1);
        float corr0 = __expf(m0 - mn0), corr1 = __expf(m1 - mn1);
        m0 = mn0; m1 = mn1;
        float ls0 = 0.f, ls1 = 0.f;
        #pragma unroll
        for (int ni = 0; ni < 8; ni++) {
            s[ni][0] = __expf(s[ni][0] - mn0);
            s[ni][1] = __expf(s[ni][1] - mn0);
            s[ni][2] = __expf(s[ni][2] - mn1);
            s[ni][3] = __expf(s[ni][3] - mn1);
            ls0 += s[ni][0] + s[ni][1];
            ls1 += s[ni][2] + s[ni][3];
        }
        #pragma unroll
        for (int o = 1; o < 4; o <<= 1) {
            ls0 += __shfl_xor_sync(0xffffffffu, ls0, o);
            ls1 += __shfl_xor_sync(0xffffffffu, ls1, o);
        }
        l0 = l0 * corr0 + ls0;
        l1 = l1 * corr1 + ls1;
        #pragma unroll
        for (int ni = 0; ni < 8; ni++) {
            acc[ni][0] *= corr0; acc[ni][1] *= corr0;
            acc[ni][2] *= corr1; acc[ni][3] *= corr1;
        }

        #pragma unroll
        for (int ni = 0; ni < 8; ni++) {
            int cb = ni * 8 + tig * 2;
            *(float2*)&Qs[(rq + g)     * AT_STR + cb] =
                make_float2(tf32f(s[ni][0]), tf32f(s[ni][1]));
            *(float2*)&Qs[(rq + g + 8) * AT_STR + cb] =
                make_float2(tf32f(s[ni][2]), tf32f(s[ni][3]));
        }
        __syncthreads();

        #pragma unroll
        for (int kb8 = 0; kb8 < 8; kb8++) {
            int kb = kb8 * 8;
            uint32_t pa[4];
            pa[0] = __float_as_uint(Qs[(rq + g)     * AT_STR + kb + tig]);
            pa[1] = __float_as_uint(Qs[(rq + g + 8) * AT_STR + kb + tig]);
            pa[2] = __float_as_uint(Qs[(rq + g)     * AT_STR + kb + tig + 4]);
            pa[3] = __float_as_uint(Qs[(rq + g + 8) * AT_STR + kb + tig + 4]);
            #pragma unroll
            for (int ni = 0; ni < 8; ni++) {
                uint32_t b0 = __float_as_uint(Vt[(ni * 8 + g) * AT_STR + kb + tig]);
                uint32_t b1 = __float_as_uint(Vt[(ni * 8 + g) * AT_STR + kb + tig + 4]);
                mma_tf32(acc[ni], pa, b0, b1);
            }
        }
    }

    float inv0 = 1.0f / l0, inv1 = 1.0f / l1;
    int row0 = b * T_SEQ + qt * 128 + rq + g;
    #pragma unroll
    for (int ni = 0; ni < 8; ni++) {
        int col = h * HDIM + ni * 8 + tig * 2;
        *(float2*)&y[(size_t)row0 * N_EMBD + col] =
            make_float2(acc[ni][0] * inv0, acc[ni][1] * inv0);
        *(float2*)&y[(size_t)(row0 + 8) * N_EMBD + col] =
            make_float2(acc[ni][2] * inv1, acc[ni][3] * inv1);
    }
}

// ---------------------------------- launcher -----------------------------------
extern "C" void kernel_launch(void* const* d_in, const int* in_sizes, int n_in,
                              void* d_out, int out_size) {
    const float* x      = (const float*)d_in[0];
    const float* ln1_g  = (const float*)d_in[1];
    const float* ln1_b  = (const float*)d_in[2];
    const float* W_attn = (const float*)d_in[3];
    const float* b_attn = (const float*)d_in[4];
    const float* W_proj = (const float*)d_in[5];
    const float* b_proj = (const float*)d_in[6];
    const float* ln2_g  = (const float*)d_in[7];
    const float* ln2_b  = (const float*)d_in[8];
    const float* W_fc   = (const float*)d_in[9];
    const float* b_fc   = (const float*)d_in[10];
    const float* W_fc2  = (const float*)d_in[11];
    const float* b_fc2  = (const float*)d_in[12];
    float* out = (float*)d_out;

    float *xn1, *qkv, *y, *x1, *xn2, *hb;
    cudaGetSymbolAddress((void**)&xn1, g_xn1);
    cudaGetSymbolAddress((void**)&qkv, g_qkv);
    cudaGetSymbolAddress((void**)&y,   g_y);
    cudaGetSymbolAddress((void**)&x1,  g_x1);
    cudaGetSymbolAddress((void**)&xn2, g_xn2);
    cudaGetSymbolAddress((void**)&hb,  g_h);

    const int attn_smem = ATT_SMEM_FLOATS * (int)sizeof(float);
    cudaFuncSetAttribute(attn_mma_kernel,
                         cudaFuncAttributeMaxDynamicSharedMemorySize, attn_smem);

    // 1) ln1
    layernorm_kernel<<<NROWS, 256>>>(x, ln1_g, ln1_b, xn1);
    // 2) qkv = xn1 @ W_attn + b_attn
    gemm_tf32_kernel<0><<<dim3(3072 / 128, NROWS / 128), 256>>>(
        xn1, W_attn, b_attn, nullptr, qkv, NROWS, 3072, 1024);
    // 3) attention (tensor cores)
    attn_mma_kernel<<<dim3(T_SEQ / 128, BATCH * NHEAD), 256, attn_smem>>>(qkv, y);
    // 4) x1 = x + y @ W_proj + b_proj
    gemm_tf32_kernel<2><<<dim3(1024 / 128, NROWS / 128), 256>>>(
        y, W_proj, b_proj, x, x1, NROWS, 1024, 1024);
    // 5) ln2
    layernorm_kernel<<<NROWS, 256>>>(x1, ln2_g, ln2_b, xn2);
    // 6) h = gelu(xn2 @ W_fc + b_fc)
    gemm_tf32_kernel<1><<<dim3(4096 / 128, NROWS / 128), 256>>>(
        xn2, W_fc, b_fc, nullptr, hb, NROWS, 4096, 1024);
    // 7) out = x1 + h @ W_fc2 + b_fc2
    gemm_tf32_kernel<2><<<dim3(1024 / 128, NROWS / 128), 256>>>(
        hb, W_fc2, b_fc2, x1, out, NROWS, 1024, 4096);
}